// round 1
// baseline (speedup 1.0000x reference)
#include <cuda_runtime.h>
#include <math.h>

#define S    3072
#define DIM  1280
#define NH   16
#define HD   80
#define SEG  512
#define NSEG 6

// Scratch (allocation-free rule: __device__ globals)
__device__ float g_q[S * DIM];
__device__ float g_k[S * DIM];
__device__ float g_v[S * DIM];
__device__ float g_ctx[S * DIM];

// ---------------------------------------------------------------------------
// SGEMM: C[M,N] = A[M,K] @ W[N,K]^T + bias[N]
// Both A and W are row-major with K contiguous ("NT" layout).
// BM=BN=128, BK=32, 256 threads, 8x8 register tile per thread.
// M=3072, N=1280, K=1280 -> all tile-divisible, no bounds checks.
// ---------------------------------------------------------------------------
__global__ __launch_bounds__(256) void gemm_nt_bias(
    const float* __restrict__ A, const float* __restrict__ W,
    const float* __restrict__ bias, float* __restrict__ C,
    int M, int N, int K)
{
    constexpr int BM = 128, BN = 128, BK = 32;
    __shared__ float As[BK][BM];
    __shared__ float Ws[BK][BN];

    const int tid = threadIdx.x;
    const int m0 = blockIdx.y * BM;
    const int n0 = blockIdx.x * BN;
    const int tx = tid & 15;   // 0..15 -> N
    const int ty = tid >> 4;   // 0..15 -> M

    float acc[8][8];
#pragma unroll
    for (int i = 0; i < 8; i++)
#pragma unroll
        for (int j = 0; j < 8; j++) acc[i][j] = 0.f;

    for (int k0 = 0; k0 < K; k0 += BK) {
        // Load tiles: 128 rows x 32 k = 1024 float4 per matrix, 4 per thread.
#pragma unroll
        for (int l = 0; l < 4; l++) {
            int idx = tid + l * 256;       // 0..1023
            int row = idx >> 3;            // 0..127
            int kc  = (idx & 7) * 4;       // 0,4,...,28
            float4 va = *(const float4*)(A + (size_t)(m0 + row) * K + k0 + kc);
            As[kc + 0][row] = va.x; As[kc + 1][row] = va.y;
            As[kc + 2][row] = va.z; As[kc + 3][row] = va.w;
            float4 vw = *(const float4*)(W + (size_t)(n0 + row) * K + k0 + kc);
            Ws[kc + 0][row] = vw.x; Ws[kc + 1][row] = vw.y;
            Ws[kc + 2][row] = vw.z; Ws[kc + 3][row] = vw.w;
        }
        __syncthreads();

#pragma unroll
        for (int kk = 0; kk < BK; kk++) {
            float a[8], b[8];
#pragma unroll
            for (int i = 0; i < 8; i++) a[i] = As[kk][ty * 8 + i];
#pragma unroll
            for (int j = 0; j < 8; j++) b[j] = Ws[kk][tx * 8 + j];
#pragma unroll
            for (int i = 0; i < 8; i++)
#pragma unroll
                for (int j = 0; j < 8; j++)
                    acc[i][j] += a[i] * b[j];
        }
        __syncthreads();
    }

#pragma unroll
    for (int i = 0; i < 8; i++) {
        int m = m0 + ty * 8 + i;
#pragma unroll
        for (int j = 0; j < 8; j += 4) {
            int n = n0 + tx * 8 + j;
            float4 o;
            o.x = acc[i][j + 0] + bias[n + 0];
            o.y = acc[i][j + 1] + bias[n + 1];
            o.z = acc[i][j + 2] + bias[n + 2];
            o.w = acc[i][j + 3] + bias[n + 3];
            *(float4*)(C + (size_t)m * N + n) = o;
        }
    }
}

// ---------------------------------------------------------------------------
// RoPE in-place on g_q, g_k.
// pair (d, d+40) within each head; cos/sin shape [S, 80] with [:,40:]==[:,:40].
// ---------------------------------------------------------------------------
__global__ void rope_kernel(const float* __restrict__ cosb,
                            const float* __restrict__ sinb)
{
    const int s = blockIdx.x;
    for (int p = threadIdx.x; p < NH * (HD / 2); p += blockDim.x) {
        int h = p / (HD / 2);
        int d = p % (HD / 2);
        float c  = cosb[s * HD + d];
        float sn = sinb[s * HD + d];
        size_t base = (size_t)s * DIM + h * HD + d;
        float q1 = g_q[base], q2 = g_q[base + HD / 2];
        g_q[base]          = q1 * c - q2 * sn;
        g_q[base + HD / 2] = q2 * c + q1 * sn;
        float k1 = g_k[base], k2 = g_k[base + HD / 2];
        g_k[base]          = k1 * c - k2 * sn;
        g_k[base + HD / 2] = k2 * c + k1 * sn;
    }
}

// ---------------------------------------------------------------------------
// Attention: block-diagonal (6 segments of 512), per-head softmax(QK^T/sqrt(80))V.
// Grid: (qtile=16, head=16, seg=6). Block: 256 threads, 32 query rows.
// Full 32x512 score matrix in dynamic SMEM (padded stride 513 to kill bank
// conflicts on the strided writes). K/V staged via SMEM in 64-row chunks
// (padded stride 81).
// ---------------------------------------------------------------------------
__global__ __launch_bounds__(256) void attn_kernel(float* __restrict__ ctx)
{
    constexpr int QM = 32;   // query rows per block
    constexpr int CH = 64;   // K/V chunk rows
    extern __shared__ float sm[];
    float* Qs  = sm;                       // QM * 81
    float* KVs = Qs + QM * 81;             // CH * 81
    float* Sc  = KVs + CH * 81;            // QM * 513
    float* inv = Sc + QM * 513;            // QM

    const int tid = threadIdx.x;
    const int qt  = blockIdx.x;            // 0..15
    const int h   = blockIdx.y;            // 0..15
    const int sg  = blockIdx.z;            // 0..5
    const int s0  = sg * SEG;
    const int q0  = s0 + qt * QM;
    const int off = h * HD;

    // Load Q tile
    for (int l = tid; l < QM * HD; l += 256) {
        int i = l / HD, d = l % HD;
        Qs[i * 81 + d] = g_q[(size_t)(q0 + i) * DIM + off + d];
    }
    __syncthreads();

    const float scale = 0.11180339887498949f;  // 1/sqrt(80)

    // Scores: QM x SEG, chunked over keys
    for (int ch = 0; ch < SEG / CH; ch++) {
        for (int l = tid; l < CH * HD; l += 256) {
            int j = l / HD, d = l % HD;
            KVs[j * 81 + d] = g_k[(size_t)(s0 + ch * CH + j) * DIM + off + d];
        }
        __syncthreads();
#pragma unroll
        for (int t = 0; t < (QM * CH) / 256; t++) {  // 8
            int idx = t * 256 + tid;
            int i = idx & (QM - 1);
            int j = idx >> 5;
            const float* qp = Qs + i * 81;
            const float* kp = KVs + j * 81;
            float a = 0.f;
#pragma unroll
            for (int d = 0; d < HD; d++) a += qp[d] * kp[d];
            Sc[i * 513 + ch * CH + j] = a * scale;
        }
        __syncthreads();
    }

    // Softmax per row (one warp handles 4 rows)
    const int warp = tid >> 5, lane = tid & 31;
    for (int i = warp; i < QM; i += 8) {
        float m = -1e30f;
        for (int j = lane; j < SEG; j += 32) m = fmaxf(m, Sc[i * 513 + j]);
#pragma unroll
        for (int o = 16; o; o >>= 1) m = fmaxf(m, __shfl_xor_sync(~0u, m, o));
        float sum = 0.f;
        for (int j = lane; j < SEG; j += 32) {
            float e = __expf(Sc[i * 513 + j] - m);
            Sc[i * 513 + j] = e;
            sum += e;
        }
#pragma unroll
        for (int o = 16; o; o >>= 1) sum += __shfl_xor_sync(~0u, sum, o);
        if (lane == 0) inv[i] = 1.f / sum;
    }
    __syncthreads();

    // PV: out[QM][HD], 10 outputs per thread, V chunked through SMEM
    float acc[10];
#pragma unroll
    for (int r = 0; r < 10; r++) acc[r] = 0.f;

    for (int ch = 0; ch < SEG / CH; ch++) {
        for (int l = tid; l < CH * HD; l += 256) {
            int j = l / HD, d = l % HD;
            KVs[j * 81 + d] = g_v[(size_t)(s0 + ch * CH + j) * DIM + off + d];
        }
        __syncthreads();
#pragma unroll
        for (int r = 0; r < 10; r++) {
            int flat = tid + r * 256;
            int i = flat / HD;
            int d = flat % HD;
            const float* sp = Sc + i * 513 + ch * CH;
            const float* vp = KVs + d;
            float a = acc[r];
#pragma unroll
            for (int j = 0; j < CH; j++) a += sp[j] * vp[j * 81];
            acc[r] = a;
        }
        __syncthreads();
    }

#pragma unroll
    for (int r = 0; r < 10; r++) {
        int flat = tid + r * 256;
        int i = flat / HD;
        int d = flat % HD;
        ctx[(size_t)(q0 + i) * DIM + off + d] = acc[r] * inv[i];
    }
}

// ---------------------------------------------------------------------------
extern "C" void kernel_launch(void* const* d_in, const int* in_sizes, int n_in,
                              void* d_out, int out_size)
{
    const float* hs   = (const float*)d_in[0];
    const float* cosb = (const float*)d_in[1];
    const float* sinb = (const float*)d_in[2];
    const float* wq   = (const float*)d_in[3];
    const float* bq   = (const float*)d_in[4];
    const float* wk   = (const float*)d_in[5];
    const float* bk   = (const float*)d_in[6];
    const float* wv   = (const float*)d_in[7];
    const float* bv   = (const float*)d_in[8];
    const float* wo   = (const float*)d_in[9];
    const float* bo   = (const float*)d_in[10];
    float* out = (float*)d_out;

    float *qp, *kp, *vp, *cp;
    cudaGetSymbolAddress((void**)&qp, g_q);
    cudaGetSymbolAddress((void**)&kp, g_k);
    cudaGetSymbolAddress((void**)&vp, g_v);
    cudaGetSymbolAddress((void**)&cp, g_ctx);

    const int smem_attn = (32 * 81 + 64 * 81 + 32 * 513 + 32) * (int)sizeof(float);
    cudaFuncSetAttribute(attn_kernel,
                         cudaFuncAttributeMaxDynamicSharedMemorySize, smem_attn);

    dim3 ggrid(DIM / 128, S / 128);
    gemm_nt_bias<<<ggrid, 256>>>(hs, wq, bq, qp, S, DIM, DIM);
    gemm_nt_bias<<<ggrid, 256>>>(hs, wk, bk, kp, S, DIM, DIM);
    gemm_nt_bias<<<ggrid, 256>>>(hs, wv, bv, vp, S, DIM, DIM);

    rope_kernel<<<S, 256>>>(cosb, sinb);

    attn_kernel<<<dim3(SEG / 32, NH, NSEG), 256, smem_attn>>>(cp);

    gemm_nt_bias<<<ggrid, 256>>>(cp, wo, bo, out, S, DIM, DIM);
}

// round 4
// speedup vs baseline: 1.6963x; 1.6963x over previous
#include <cuda_runtime.h>
#include <cuda_bf16.h>
#include <cstdint>
#include <math.h>

#define S    3072
#define DIM  1280
#define NH   16
#define HD   80
#define SEG  512
#define NSEG 6

// ---------------- scratch (__device__ globals; no allocs allowed) ----------
__device__ float g_q[S * DIM];
__device__ float g_k[S * DIM];
__device__ float g_v[S * DIM];
__device__ float g_ctx[S * DIM];

__device__ __nv_bfloat16 g_ah[S * DIM];       // hidden_states hi
__device__ __nv_bfloat16 g_al[S * DIM];       // hidden_states lo
__device__ __nv_bfloat16 g_wh[4 * DIM * DIM]; // wq,wk,wv,wo hi
__device__ __nv_bfloat16 g_wl[4 * DIM * DIM]; // wq,wk,wv,wo lo
__device__ __nv_bfloat16 g_ch[S * DIM];       // ctx hi
__device__ __nv_bfloat16 g_cl[S * DIM];       // ctx lo

// ---------------- PTX helpers (all non-arch-specific: sm_80 era) -----------
__device__ __forceinline__ uint32_t smem_u32(const void* p) {
    uint32_t a;
    asm("{ .reg .u64 t; cvta.to.shared.u64 t, %1; cvt.u32.u64 %0, t; }"
        : "=r"(a) : "l"(p));
    return a;
}

__device__ __forceinline__ void ldsm4(uint32_t* r, uint32_t addr) {
    asm volatile("ldmatrix.sync.aligned.m8n8.x4.shared.b16 {%0,%1,%2,%3}, [%4];"
                 : "=r"(r[0]), "=r"(r[1]), "=r"(r[2]), "=r"(r[3]) : "r"(addr));
}
__device__ __forceinline__ void ldsm2(uint32_t* r, uint32_t addr) {
    asm volatile("ldmatrix.sync.aligned.m8n8.x2.shared.b16 {%0,%1}, [%2];"
                 : "=r"(r[0]), "=r"(r[1]) : "r"(addr));
}

__device__ __forceinline__ void mma16816(float* d, const uint32_t* a, const uint32_t* b) {
    asm volatile(
        "mma.sync.aligned.m16n8k16.row.col.f32.bf16.bf16.f32 "
        "{%0,%1,%2,%3}, {%4,%5,%6,%7}, {%8,%9}, {%0,%1,%2,%3};"
        : "+f"(d[0]), "+f"(d[1]), "+f"(d[2]), "+f"(d[3])
        : "r"(a[0]), "r"(a[1]), "r"(a[2]), "r"(a[3]), "r"(b[0]), "r"(b[1]));
}

#define CP_ASYNC16(dst, src) \
    asm volatile("cp.async.cg.shared.global [%0], [%1], 16;" :: "r"(dst), "l"(src))
#define CP_COMMIT() asm volatile("cp.async.commit_group;")
#define CP_WAIT1()  asm volatile("cp.async.wait_group 1;")
#define CP_WAIT0()  asm volatile("cp.async.wait_group 0;")

// ---------------- fp32 -> bf16 hi/lo split kernels --------------------------
__global__ void split_hs(const float* __restrict__ src,
                         __nv_bfloat16* __restrict__ hi,
                         __nv_bfloat16* __restrict__ lo, int n) {
    int i = blockIdx.x * blockDim.x + threadIdx.x;
    if (i < n) {
        float v = src[i];
        __nv_bfloat16 h = __float2bfloat16(v);
        hi[i] = h;
        lo[i] = __float2bfloat16(v - __bfloat162float(h));
    }
}

__global__ void split_w4(const float* __restrict__ s0, const float* __restrict__ s1,
                         const float* __restrict__ s2, const float* __restrict__ s3,
                         __nv_bfloat16* __restrict__ hi,
                         __nv_bfloat16* __restrict__ lo) {
    int z = blockIdx.y;
    const float* s = (z == 0) ? s0 : (z == 1) ? s1 : (z == 2) ? s2 : s3;
    size_t base = (size_t)z * DIM * DIM;
    int i = blockIdx.x * blockDim.x + threadIdx.x;
    float v = s[i];
    __nv_bfloat16 h = __float2bfloat16(v);
    hi[base + i] = h;
    lo[base + i] = __float2bfloat16(v - __bfloat162float(h));
}

// ---------------- HMMA bf16x3 GEMM ------------------------------------------
// C[M,N] = A[M,K] @ W[N,K]^T + bias; acc += Ah*Wh + Ah*Wl + Al*Wh (fp32 acc).
// Tile 128x128, BK=32. 8 warps (2 m x 4 n), warp tile 64x32.
// Smem: per stage 4 tiles (Ah,Al,Wh,Wl) of 128 rows x 32 bf16, row stride 80B.
#define GBM 128
#define GBN 128
#define NCHUNK (DIM / 32)            // 40
#define TSTRIDE 80                   // bytes per smem row (conflict-free ldmatrix)
#define TILE_B  (128 * TSTRIDE)      // 10240
#define STAGE_B (4 * TILE_B)         // 40960
#define GEMM_SMEM (2 * STAGE_B)      // 81920

__global__ __launch_bounds__(256) void gemm_hmma(
    const __nv_bfloat16* __restrict__ Ahi, const __nv_bfloat16* __restrict__ Alo,
    const __nv_bfloat16* __restrict__ Whi_base, const __nv_bfloat16* __restrict__ Wlo_base,
    int zoff,
    const float* __restrict__ bias0, const float* __restrict__ bias1, const float* __restrict__ bias2,
    float* __restrict__ C0, float* __restrict__ C1, float* __restrict__ C2)
{
    extern __shared__ char smem[];
    const uint32_t sb = smem_u32(smem);
    const int tid  = threadIdx.x;
    const int wid  = tid >> 5;
    const int lane = tid & 31;

    const int z = blockIdx.z;
    const __nv_bfloat16* Wh = Whi_base + (size_t)(zoff + z) * DIM * DIM;
    const __nv_bfloat16* Wl = Wlo_base + (size_t)(zoff + z) * DIM * DIM;
    const float* bias = (z == 0) ? bias0 : (z == 1) ? bias1 : bias2;
    float* C = (z == 0) ? C0 : (z == 1) ? C1 : C2;

    const int m0 = blockIdx.y * GBM;
    const int n0 = blockIdx.x * GBN;

    const int wm = (wid & 1) * 64;   // warp m offset in tile
    const int wn = (wid >> 1) * 32;  // warp n offset in tile

    // global->smem load assignment: 4 groups of 64 threads, one tile each.
    const int tile = tid >> 6;
    const int t64  = tid & 63;
    const char* gsrc;
    if (tile == 0)      gsrc = (const char*)(Ahi + (size_t)m0 * DIM);
    else if (tile == 1) gsrc = (const char*)(Alo + (size_t)m0 * DIM);
    else if (tile == 2) gsrc = (const char*)(Wh  + (size_t)n0 * DIM);
    else                gsrc = (const char*)(Wl  + (size_t)n0 * DIM);
    const uint32_t sdst0 = sb + tile * TILE_B;

    float acc[4][4][4];
#pragma unroll
    for (int mt = 0; mt < 4; mt++)
#pragma unroll
        for (int nt = 0; nt < 4; nt++)
#pragma unroll
            for (int i = 0; i < 4; i++) acc[mt][nt][i] = 0.f;

    // preload chunk 0
    {
        const char* s = gsrc;
        uint32_t d = sdst0;
#pragma unroll
        for (int i = 0; i < 8; i++) {
            int idx = i * 64 + t64;
            int row = idx >> 2, c16 = idx & 3;
            CP_ASYNC16(d + row * TSTRIDE + c16 * 16,
                       s + (size_t)row * (DIM * 2) + c16 * 16);
        }
        CP_COMMIT();
    }

    // per-k-step ldmatrix address components (constant across chunks)
    const int arow = lane & 15;
    const int acolh = (lane >> 4) * 16;          // 0 or 16 bytes
    const int brow = lane & 7;
    const int bcolh = ((lane >> 3) & 1) * 16;    // 0 or 16 bytes

    for (int c = 0; c < NCHUNK; c++) {
        if (c + 1 < NCHUNK) {
            const char* s = gsrc + (size_t)(c + 1) * 64;  // 32 bf16 = 64B per chunk
            uint32_t d = sdst0 + ((c + 1) & 1) * STAGE_B;
#pragma unroll
            for (int i = 0; i < 8; i++) {
                int idx = i * 64 + t64;
                int row = idx >> 2, c16 = idx & 3;
                CP_ASYNC16(d + row * TSTRIDE + c16 * 16,
                           s + (size_t)row * (DIM * 2) + c16 * 16);
            }
            CP_COMMIT();
            CP_WAIT1();
        } else {
            CP_WAIT0();
        }
        __syncthreads();

        const uint32_t stage = sb + (c & 1) * STAGE_B;
        const uint32_t sAh = stage;
        const uint32_t sAl = stage + TILE_B;
        const uint32_t sWh = stage + 2 * TILE_B;
        const uint32_t sWl = stage + 3 * TILE_B;

#pragma unroll
        for (int ks = 0; ks < 2; ks++) {
            uint32_t ah[4][4], al[4][4], bh[4][2], bl[4][2];
            const int acol = ks * 32 + acolh;
            const int bcol = ks * 32 + bcolh;
#pragma unroll
            for (int mt = 0; mt < 4; mt++) {
                uint32_t off = (uint32_t)((wm + mt * 16 + arow) * TSTRIDE + acol);
                ldsm4(ah[mt], sAh + off);
                ldsm4(al[mt], sAl + off);
            }
#pragma unroll
            for (int nt = 0; nt < 4; nt++) {
                uint32_t off = (uint32_t)((wn + nt * 8 + brow) * TSTRIDE + bcol);
                ldsm2(bh[nt], sWh + off);
                ldsm2(bl[nt], sWl + off);
            }
#pragma unroll
            for (int mt = 0; mt < 4; mt++)
#pragma unroll
                for (int nt = 0; nt < 4; nt++) {
                    mma16816(acc[mt][nt], ah[mt], bh[nt]);
                    mma16816(acc[mt][nt], ah[mt], bl[nt]);
                    mma16816(acc[mt][nt], al[mt], bh[nt]);
                }
        }
        __syncthreads();
    }

    // epilogue: add bias, store fp32
    const int r0 = lane >> 2;
    const int c0 = (lane & 3) * 2;
#pragma unroll
    for (int mt = 0; mt < 4; mt++) {
#pragma unroll
        for (int nt = 0; nt < 4; nt++) {
            int gm = m0 + wm + mt * 16 + r0;
            int gn = n0 + wn + nt * 8 + c0;
            float2 bv = *(const float2*)(bias + gn);
            float2 o0, o1;
            o0.x = acc[mt][nt][0] + bv.x;
            o0.y = acc[mt][nt][1] + bv.y;
            o1.x = acc[mt][nt][2] + bv.x;
            o1.y = acc[mt][nt][3] + bv.y;
            *(float2*)(C + (size_t)gm * DIM + gn) = o0;
            *(float2*)(C + (size_t)(gm + 8) * DIM + gn) = o1;
        }
    }
}

// ---------------- RoPE (unchanged) ------------------------------------------
__global__ void rope_kernel(const float* __restrict__ cosb,
                            const float* __restrict__ sinb)
{
    const int s = blockIdx.x;
    for (int p = threadIdx.x; p < NH * (HD / 2); p += blockDim.x) {
        int h = p / (HD / 2);
        int d = p % (HD / 2);
        float c  = cosb[s * HD + d];
        float sn = sinb[s * HD + d];
        size_t base = (size_t)s * DIM + h * HD + d;
        float q1 = g_q[base], q2 = g_q[base + HD / 2];
        g_q[base]          = q1 * c - q2 * sn;
        g_q[base + HD / 2] = q2 * c + q1 * sn;
        float k1 = g_k[base], k2 = g_k[base + HD / 2];
        g_k[base]          = k1 * c - k2 * sn;
        g_k[base + HD / 2] = k2 * c + k1 * sn;
    }
}

// ---------------- attention (unchanged) --------------------------------------
__global__ __launch_bounds__(256) void attn_kernel(float* __restrict__ ctx)
{
    constexpr int QM = 32;
    constexpr int CH = 64;
    extern __shared__ float sm[];
    float* Qs  = sm;
    float* KVs = Qs + QM * 81;
    float* Sc  = KVs + CH * 81;
    float* inv = Sc + QM * 513;

    const int tid = threadIdx.x;
    const int qt  = blockIdx.x;
    const int h   = blockIdx.y;
    const int sg  = blockIdx.z;
    const int s0  = sg * SEG;
    const int q0  = s0 + qt * QM;
    const int off = h * HD;

    for (int l = tid; l < QM * HD; l += 256) {
        int i = l / HD, d = l % HD;
        Qs[i * 81 + d] = g_q[(size_t)(q0 + i) * DIM + off + d];
    }
    __syncthreads();

    const float scale = 0.11180339887498949f;

    for (int ch = 0; ch < SEG / CH; ch++) {
        for (int l = tid; l < CH * HD; l += 256) {
            int j = l / HD, d = l % HD;
            KVs[j * 81 + d] = g_k[(size_t)(s0 + ch * CH + j) * DIM + off + d];
        }
        __syncthreads();
#pragma unroll
        for (int t = 0; t < (QM * CH) / 256; t++) {
            int idx = t * 256 + tid;
            int i = idx & (QM - 1);
            int j = idx >> 5;
            const float* qp = Qs + i * 81;
            const float* kp = KVs + j * 81;
            float a = 0.f;
#pragma unroll
            for (int d = 0; d < HD; d++) a += qp[d] * kp[d];
            Sc[i * 513 + ch * CH + j] = a * scale;
        }
        __syncthreads();
    }

    const int warp = tid >> 5, lane = tid & 31;
    for (int i = warp; i < QM; i += 8) {
        float m = -1e30f;
        for (int j = lane; j < SEG; j += 32) m = fmaxf(m, Sc[i * 513 + j]);
#pragma unroll
        for (int o = 16; o; o >>= 1) m = fmaxf(m, __shfl_xor_sync(~0u, m, o));
        float sum = 0.f;
        for (int j = lane; j < SEG; j += 32) {
            float e = __expf(Sc[i * 513 + j] - m);
            Sc[i * 513 + j] = e;
            sum += e;
        }
#pragma unroll
        for (int o = 16; o; o >>= 1) sum += __shfl_xor_sync(~0u, sum, o);
        if (lane == 0) inv[i] = 1.f / sum;
    }
    __syncthreads();

    float acc[10];
#pragma unroll
    for (int r = 0; r < 10; r++) acc[r] = 0.f;

    for (int ch = 0; ch < SEG / CH; ch++) {
        for (int l = tid; l < CH * HD; l += 256) {
            int j = l / HD, d = l % HD;
            KVs[j * 81 + d] = g_v[(size_t)(s0 + ch * CH + j) * DIM + off + d];
        }
        __syncthreads();
#pragma unroll
        for (int r = 0; r < 10; r++) {
            int flat = tid + r * 256;
            int i = flat / HD;
            int d = flat % HD;
            const float* sp = Sc + i * 513 + ch * CH;
            const float* vp = KVs + d;
            float a = acc[r];
#pragma unroll
            for (int j = 0; j < CH; j++) a += sp[j] * vp[j * 81];
            acc[r] = a;
        }
        __syncthreads();
    }

#pragma unroll
    for (int r = 0; r < 10; r++) {
        int flat = tid + r * 256;
        int i = flat / HD;
        int d = flat % HD;
        ctx[(size_t)(q0 + i) * DIM + off + d] = acc[r] * inv[i];
    }
}

// ---------------------------------------------------------------------------
extern "C" void kernel_launch(void* const* d_in, const int* in_sizes, int n_in,
                              void* d_out, int out_size)
{
    const float* hs   = (const float*)d_in[0];
    const float* cosb = (const float*)d_in[1];
    const float* sinb = (const float*)d_in[2];
    const float* wq   = (const float*)d_in[3];
    const float* bq   = (const float*)d_in[4];
    const float* wk   = (const float*)d_in[5];
    const float* bk   = (const float*)d_in[6];
    const float* wv   = (const float*)d_in[7];
    const float* bv   = (const float*)d_in[8];
    const float* wo   = (const float*)d_in[9];
    const float* bo   = (const float*)d_in[10];
    float* out = (float*)d_out;

    float *qp, *kp, *vp, *cp;
    cudaGetSymbolAddress((void**)&qp, g_q);
    cudaGetSymbolAddress((void**)&kp, g_k);
    cudaGetSymbolAddress((void**)&vp, g_v);
    cudaGetSymbolAddress((void**)&cp, g_ctx);
    __nv_bfloat16 *ah, *al, *wh, *wl, *ch, *cl;
    cudaGetSymbolAddress((void**)&ah, g_ah);
    cudaGetSymbolAddress((void**)&al, g_al);
    cudaGetSymbolAddress((void**)&wh, g_wh);
    cudaGetSymbolAddress((void**)&wl, g_wl);
    cudaGetSymbolAddress((void**)&ch, g_ch);
    cudaGetSymbolAddress((void**)&cl, g_cl);

    const int smem_attn = (32 * 81 + 64 * 81 + 32 * 513 + 32) * (int)sizeof(float);
    cudaFuncSetAttribute(gemm_hmma,
                         cudaFuncAttributeMaxDynamicSharedMemorySize, GEMM_SMEM);
    cudaFuncSetAttribute(attn_kernel,
                         cudaFuncAttributeMaxDynamicSharedMemorySize, smem_attn);

    // 1) split inputs to bf16 hi/lo
    split_hs<<<(S * DIM) / 256, 256>>>(hs, ah, al, S * DIM);
    split_w4<<<dim3((DIM * DIM) / 256, 4), 256>>>(wq, wk, wv, wo, wh, wl);

    // 2) QKV projections (one launch, z = q/k/v)
    gemm_hmma<<<dim3(DIM / GBN, S / GBM, 3), 256, GEMM_SMEM>>>(
        ah, al, wh, wl, 0, bq, bk, bv, qp, kp, vp);

    // 3) RoPE
    rope_kernel<<<S, 256>>>(cosb, sinb);

    // 4) attention
    attn_kernel<<<dim3(SEG / 32, NH, NSEG), 256, smem_attn>>>(cp);

    // 5) ctx -> bf16 hi/lo, then O projection
    split_hs<<<(S * DIM) / 256, 256>>>(cp, ch, cl, S * DIM);
    gemm_hmma<<<dim3(DIM / GBN, S / GBM, 1), 256, GEMM_SMEM>>>(
        ch, cl, wh, wl, 3, bo, bo, bo, out, out, out);
}

// round 5
// speedup vs baseline: 4.1694x; 2.4579x over previous
#include <cuda_runtime.h>
#include <cuda_bf16.h>
#include <cstdint>
#include <math.h>

#define S    3072
#define DIM  1280
#define NH   16
#define HD   80
#define SEG  512
#define NSEG 6

// ---------------- scratch (__device__ globals; no allocs allowed) ----------
__device__ float g_q[S * DIM];
__device__ float g_k[S * DIM];
__device__ float g_v[S * DIM];

__device__ __nv_bfloat16 g_ah[S * DIM];       // hidden_states hi
__device__ __nv_bfloat16 g_al[S * DIM];       // hidden_states lo
__device__ __nv_bfloat16 g_wh[4 * DIM * DIM]; // wq,wk,wv,wo hi
__device__ __nv_bfloat16 g_wl[4 * DIM * DIM]; // wq,wk,wv,wo lo
__device__ __nv_bfloat16 g_ch[S * DIM];       // ctx hi
__device__ __nv_bfloat16 g_cl[S * DIM];       // ctx lo

// per-head packed q/k/v (post-rope, q pre-scaled), hi/lo: [NH][S][80]
__device__ __nv_bfloat16 g_qh[NH * S * HD];
__device__ __nv_bfloat16 g_ql[NH * S * HD];
__device__ __nv_bfloat16 g_kh[NH * S * HD];
__device__ __nv_bfloat16 g_kl[NH * S * HD];
__device__ __nv_bfloat16 g_vh[NH * S * HD];
__device__ __nv_bfloat16 g_vl[NH * S * HD];

// ---------------- PTX helpers (all non-arch-specific: sm_80 era) -----------
__device__ __forceinline__ uint32_t smem_u32(const void* p) {
    uint32_t a;
    asm("{ .reg .u64 t; cvta.to.shared.u64 t, %1; cvt.u32.u64 %0, t; }"
        : "=r"(a) : "l"(p));
    return a;
}

__device__ __forceinline__ void ldsm4(uint32_t* r, uint32_t addr) {
    asm volatile("ldmatrix.sync.aligned.m8n8.x4.shared.b16 {%0,%1,%2,%3}, [%4];"
                 : "=r"(r[0]), "=r"(r[1]), "=r"(r[2]), "=r"(r[3]) : "r"(addr));
}
__device__ __forceinline__ void ldsm2(uint32_t* r, uint32_t addr) {
    asm volatile("ldmatrix.sync.aligned.m8n8.x2.shared.b16 {%0,%1}, [%2];"
                 : "=r"(r[0]), "=r"(r[1]) : "r"(addr));
}
__device__ __forceinline__ void ldsm2t(uint32_t* r, uint32_t addr) {
    asm volatile("ldmatrix.sync.aligned.m8n8.x2.trans.shared.b16 {%0,%1}, [%2];"
                 : "=r"(r[0]), "=r"(r[1]) : "r"(addr));
}

__device__ __forceinline__ void mma16816(float* d, const uint32_t* a, const uint32_t* b) {
    asm volatile(
        "mma.sync.aligned.m16n8k16.row.col.f32.bf16.bf16.f32 "
        "{%0,%1,%2,%3}, {%4,%5,%6,%7}, {%8,%9}, {%0,%1,%2,%3};"
        : "+f"(d[0]), "+f"(d[1]), "+f"(d[2]), "+f"(d[3])
        : "r"(a[0]), "r"(a[1]), "r"(a[2]), "r"(a[3]), "r"(b[0]), "r"(b[1]));
}

#define CP_ASYNC16(dst, src) \
    asm volatile("cp.async.cg.shared.global [%0], [%1], 16;" :: "r"(dst), "l"(src))
#define CP_COMMIT() asm volatile("cp.async.commit_group;")
#define CP_WAIT1()  asm volatile("cp.async.wait_group 1;")
#define CP_WAIT0()  asm volatile("cp.async.wait_group 0;")

// ---------------- fp32 -> bf16 hi/lo split kernels --------------------------
__global__ void split_hs(const float* __restrict__ src,
                         __nv_bfloat16* __restrict__ hi,
                         __nv_bfloat16* __restrict__ lo, int n) {
    int i = blockIdx.x * blockDim.x + threadIdx.x;
    if (i < n) {
        float v = src[i];
        __nv_bfloat16 h = __float2bfloat16(v);
        hi[i] = h;
        lo[i] = __float2bfloat16(v - __bfloat162float(h));
    }
}

__global__ void split_w4(const float* __restrict__ s0, const float* __restrict__ s1,
                         const float* __restrict__ s2, const float* __restrict__ s3,
                         __nv_bfloat16* __restrict__ hi,
                         __nv_bfloat16* __restrict__ lo) {
    int z = blockIdx.y;
    const float* s = (z == 0) ? s0 : (z == 1) ? s1 : (z == 2) ? s2 : s3;
    size_t base = (size_t)z * DIM * DIM;
    int i = blockIdx.x * blockDim.x + threadIdx.x;
    float v = s[i];
    __nv_bfloat16 h = __float2bfloat16(v);
    hi[base + i] = h;
    lo[base + i] = __float2bfloat16(v - __bfloat162float(h));
}

// ---------------- HMMA bf16x3 GEMM (unchanged from round 4) -----------------
#define GBM 128
#define GBN 128
#define NCHUNK (DIM / 32)            // 40
#define TSTRIDE 80
#define TILE_B  (128 * TSTRIDE)
#define STAGE_B (4 * TILE_B)
#define GEMM_SMEM (2 * STAGE_B)

__global__ __launch_bounds__(256) void gemm_hmma(
    const __nv_bfloat16* __restrict__ Ahi, const __nv_bfloat16* __restrict__ Alo,
    const __nv_bfloat16* __restrict__ Whi_base, const __nv_bfloat16* __restrict__ Wlo_base,
    int zoff,
    const float* __restrict__ bias0, const float* __restrict__ bias1, const float* __restrict__ bias2,
    float* __restrict__ C0, float* __restrict__ C1, float* __restrict__ C2)
{
    extern __shared__ char smem[];
    const uint32_t sb = smem_u32(smem);
    const int tid  = threadIdx.x;
    const int wid  = tid >> 5;
    const int lane = tid & 31;

    const int z = blockIdx.z;
    const __nv_bfloat16* Wh = Whi_base + (size_t)(zoff + z) * DIM * DIM;
    const __nv_bfloat16* Wl = Wlo_base + (size_t)(zoff + z) * DIM * DIM;
    const float* bias = (z == 0) ? bias0 : (z == 1) ? bias1 : bias2;
    float* C = (z == 0) ? C0 : (z == 1) ? C1 : C2;

    const int m0 = blockIdx.y * GBM;
    const int n0 = blockIdx.x * GBN;

    const int wm = (wid & 1) * 64;
    const int wn = (wid >> 1) * 32;

    const int tile = tid >> 6;
    const int t64  = tid & 63;
    const char* gsrc;
    if (tile == 0)      gsrc = (const char*)(Ahi + (size_t)m0 * DIM);
    else if (tile == 1) gsrc = (const char*)(Alo + (size_t)m0 * DIM);
    else if (tile == 2) gsrc = (const char*)(Wh  + (size_t)n0 * DIM);
    else                gsrc = (const char*)(Wl  + (size_t)n0 * DIM);
    const uint32_t sdst0 = sb + tile * TILE_B;

    float acc[4][4][4];
#pragma unroll
    for (int mt = 0; mt < 4; mt++)
#pragma unroll
        for (int nt = 0; nt < 4; nt++)
#pragma unroll
            for (int i = 0; i < 4; i++) acc[mt][nt][i] = 0.f;

    {
        const char* s = gsrc;
        uint32_t d = sdst0;
#pragma unroll
        for (int i = 0; i < 8; i++) {
            int idx = i * 64 + t64;
            int row = idx >> 2, c16 = idx & 3;
            CP_ASYNC16(d + row * TSTRIDE + c16 * 16,
                       s + (size_t)row * (DIM * 2) + c16 * 16);
        }
        CP_COMMIT();
    }

    const int arow = lane & 15;
    const int acolh = (lane >> 4) * 16;
    const int brow = lane & 7;
    const int bcolh = ((lane >> 3) & 1) * 16;

    for (int c = 0; c < NCHUNK; c++) {
        if (c + 1 < NCHUNK) {
            const char* s = gsrc + (size_t)(c + 1) * 64;
            uint32_t d = sdst0 + ((c + 1) & 1) * STAGE_B;
#pragma unroll
            for (int i = 0; i < 8; i++) {
                int idx = i * 64 + t64;
                int row = idx >> 2, c16 = idx & 3;
                CP_ASYNC16(d + row * TSTRIDE + c16 * 16,
                           s + (size_t)row * (DIM * 2) + c16 * 16);
            }
            CP_COMMIT();
            CP_WAIT1();
        } else {
            CP_WAIT0();
        }
        __syncthreads();

        const uint32_t stage = sb + (c & 1) * STAGE_B;
        const uint32_t sAh = stage;
        const uint32_t sAl = stage + TILE_B;
        const uint32_t sWh = stage + 2 * TILE_B;
        const uint32_t sWl = stage + 3 * TILE_B;

#pragma unroll
        for (int ks = 0; ks < 2; ks++) {
            uint32_t ah[4][4], al[4][4], bh[4][2], bl[4][2];
            const int acol = ks * 32 + acolh;
            const int bcol = ks * 32 + bcolh;
#pragma unroll
            for (int mt = 0; mt < 4; mt++) {
                uint32_t off = (uint32_t)((wm + mt * 16 + arow) * TSTRIDE + acol);
                ldsm4(ah[mt], sAh + off);
                ldsm4(al[mt], sAl + off);
            }
#pragma unroll
            for (int nt = 0; nt < 4; nt++) {
                uint32_t off = (uint32_t)((wn + nt * 8 + brow) * TSTRIDE + bcol);
                ldsm2(bh[nt], sWh + off);
                ldsm2(bl[nt], sWl + off);
            }
#pragma unroll
            for (int mt = 0; mt < 4; mt++)
#pragma unroll
                for (int nt = 0; nt < 4; nt++) {
                    mma16816(acc[mt][nt], ah[mt], bh[nt]);
                    mma16816(acc[mt][nt], ah[mt], bl[nt]);
                    mma16816(acc[mt][nt], al[mt], bh[nt]);
                }
        }
        __syncthreads();
    }

    const int r0 = lane >> 2;
    const int c0 = (lane & 3) * 2;
#pragma unroll
    for (int mt = 0; mt < 4; mt++) {
#pragma unroll
        for (int nt = 0; nt < 4; nt++) {
            int gm = m0 + wm + mt * 16 + r0;
            int gn = n0 + wn + nt * 8 + c0;
            float2 bv = *(const float2*)(bias + gn);
            float2 o0, o1;
            o0.x = acc[mt][nt][0] + bv.x;
            o0.y = acc[mt][nt][1] + bv.y;
            o1.x = acc[mt][nt][2] + bv.x;
            o1.y = acc[mt][nt][3] + bv.y;
            *(float2*)(C + (size_t)gm * DIM + gn) = o0;
            *(float2*)(C + (size_t)(gm + 8) * DIM + gn) = o1;
        }
    }
}

// ---------------- pack: rope + scale + split + per-head relayout ------------
__global__ void pack_qkv(const float* __restrict__ cosb,
                         const float* __restrict__ sinb)
{
    const int s = blockIdx.x;
    const int tid = threadIdx.x;
    const float scale = 0.11180339887498949f;  // 1/sqrt(80)

    for (int p = tid; p < NH * 40; p += 256) {
        int h = p / 40, d = p % 40;
        float c  = cosb[s * HD + d];
        float sn = sinb[s * HD + d];
        size_t ib = (size_t)s * DIM + h * HD + d;
        size_t ob = ((size_t)h * S + s) * HD + d;

        float q1 = g_q[ib], q2 = g_q[ib + 40];
        float qo1 = (q1 * c - q2 * sn) * scale;
        float qo2 = (q2 * c + q1 * sn) * scale;
        __nv_bfloat16 h1 = __float2bfloat16(qo1);
        __nv_bfloat16 h2 = __float2bfloat16(qo2);
        g_qh[ob]      = h1;
        g_qh[ob + 40] = h2;
        g_ql[ob]      = __float2bfloat16(qo1 - __bfloat162float(h1));
        g_ql[ob + 40] = __float2bfloat16(qo2 - __bfloat162float(h2));

        float k1 = g_k[ib], k2 = g_k[ib + 40];
        float ko1 = k1 * c - k2 * sn;
        float ko2 = k2 * c + k1 * sn;
        __nv_bfloat16 kh1 = __float2bfloat16(ko1);
        __nv_bfloat16 kh2 = __float2bfloat16(ko2);
        g_kh[ob]      = kh1;
        g_kh[ob + 40] = kh2;
        g_kl[ob]      = __float2bfloat16(ko1 - __bfloat162float(kh1));
        g_kl[ob + 40] = __float2bfloat16(ko2 - __bfloat162float(kh2));
    }

    for (int e = tid; e < DIM; e += 256) {
        int h = e / HD, d = e % HD;
        float v = g_v[(size_t)s * DIM + e];
        __nv_bfloat16 vh = __float2bfloat16(v);
        size_t ob = ((size_t)h * S + s) * HD + d;
        g_vh[ob] = vh;
        g_vl[ob] = __float2bfloat16(v - __bfloat162float(vh));
    }
}

// ---------------- flash attention via HMMA bf16x3 ---------------------------
// CTA: 64 q rows, one head, one segment. 8 chunks of 64 keys.
// smem offsets (bytes); qk rows padded to 176B, S to 264B, P to 144B.
#define AOFF_QH 0
#define AOFF_QL (AOFF_QH + 64 * 176)
#define AOFF_KH (AOFF_QL + 64 * 176)
#define AOFF_KL (AOFF_KH + 64 * 176)
#define AOFF_VH (AOFF_KL + 64 * 176)
#define AOFF_VL (AOFF_VH + 64 * 176)
#define AOFF_S  (AOFF_VL + 64 * 176)
#define AOFF_PH (AOFF_S  + 64 * 264)
#define AOFF_PL (AOFF_PH + 64 * 144)
#define AOFF_ST (AOFF_PL + 64 * 144)
#define ATTN_SMEM (AOFF_ST + 3 * 64 * 4)    // 103,680 B

__global__ __launch_bounds__(256) void attn_mma(__nv_bfloat16* __restrict__ ch,
                                                __nv_bfloat16* __restrict__ cl)
{
    extern __shared__ char sm[];
    const uint32_t sb = smem_u32(sm);
    const int tid = threadIdx.x;
    const int wid = tid >> 5;
    const int lane = tid & 31;

    const int qt = blockIdx.x;          // 0..7
    const int h  = blockIdx.y;          // 0..15
    const int sg = blockIdx.z;          // 0..5
    const int s0 = sg * SEG;
    const int q0 = s0 + qt * 64;
    const size_t hb = (size_t)h * S * HD;

    float* sM = (float*)(sm + AOFF_ST);
    float* sL = sM + 64;
    float* sF = sL + 64;

    // stats init
    for (int r = tid; r < 64; r += 256) { sM[r] = -1e30f; sL[r] = 0.f; }

    // Q load (hi/lo): 2 tiles x 640 cp16
    {
        const char* sh = (const char*)(g_qh + hb + (size_t)q0 * HD);
        const char* sl = (const char*)(g_ql + hb + (size_t)q0 * HD);
#pragma unroll
        for (int i = 0; i < 5; i++) {
            int f = i * 256 + tid;
            int sel = f >= 640;
            int g = f - (sel ? 640 : 0);
            int r = g / 10, c = g - r * 10;
            CP_ASYNC16(sb + (sel ? AOFF_QL : AOFF_QH) + r * 176 + c * 16,
                       (sel ? sl : sh) + (size_t)r * 160 + c * 16);
        }
        CP_COMMIT();
    }

    const char* khp = (const char*)(g_kh + hb + (size_t)s0 * HD);
    const char* klp = (const char*)(g_kl + hb + (size_t)s0 * HD);
    const char* vhp = (const char*)(g_vh + hb + (size_t)s0 * HD);
    const char* vlp = (const char*)(g_vl + hb + (size_t)s0 * HD);

    auto issue_kv = [&](int cc) {
        const int j0 = cc * 64;
#pragma unroll
        for (int i = 0; i < 5; i++) {
            int f = i * 256 + tid;
            int sel = f >= 640;
            int g = f - (sel ? 640 : 0);
            int r = g / 10, c = g - r * 10;
            CP_ASYNC16(sb + (sel ? AOFF_KL : AOFF_KH) + r * 176 + c * 16,
                       (sel ? klp : khp) + (size_t)(j0 + r) * 160 + c * 16);
        }
        CP_COMMIT();
#pragma unroll
        for (int i = 0; i < 5; i++) {
            int f = i * 256 + tid;
            int sel = f >= 640;
            int g = f - (sel ? 640 : 0);
            int r = g / 10, c = g - r * 10;
            CP_ASYNC16(sb + (sel ? AOFF_VL : AOFF_VH) + r * 176 + c * 16,
                       (sel ? vlp : vhp) + (size_t)(j0 + r) * 160 + c * 16);
        }
        CP_COMMIT();
    };

    issue_kv(0);

    // QK warp layout: 2m x 4n over 64x64
    const int wmq = (wid & 1) * 32;
    const int wnq = (wid >> 1) * 16;
    // PV warp layout: 4m x 2n over 64x80
    const int wmp = (wid & 3) * 16;
    const int wnp = (wid >> 2) * 40;

    float acc[5][4];
#pragma unroll
    for (int nt = 0; nt < 5; nt++)
#pragma unroll
        for (int i = 0; i < 4; i++) acc[nt][i] = 0.f;

    const int arow = lane & 15;
    const int acolh = (lane >> 4) * 16;
    const int brow = lane & 7;
    const int bcolh = ((lane >> 3) & 1) * 16;

    for (int cc = 0; cc < 8; cc++) {
        CP_WAIT1();          // K (and Q on first iter) arrived
        __syncthreads();

        // ---- S = Qs K^T (bf16x3) ----
        float sa[2][2][4];
#pragma unroll
        for (int mt = 0; mt < 2; mt++)
#pragma unroll
            for (int nt = 0; nt < 2; nt++)
#pragma unroll
                for (int i = 0; i < 4; i++) sa[mt][nt][i] = 0.f;

#pragma unroll
        for (int ks = 0; ks < 5; ks++) {
            uint32_t aH[2][4], aL[2][4], bH[2][2], bL[2][2];
            const int acol = ks * 32 + acolh;
            const int bcol = ks * 32 + bcolh;
#pragma unroll
            for (int mt = 0; mt < 2; mt++) {
                uint32_t off = (uint32_t)((wmq + mt * 16 + arow) * 176 + acol);
                ldsm4(aH[mt], sb + AOFF_QH + off);
                ldsm4(aL[mt], sb + AOFF_QL + off);
            }
#pragma unroll
            for (int nt = 0; nt < 2; nt++) {
                uint32_t off = (uint32_t)((wnq + nt * 8 + brow) * 176 + bcol);
                ldsm2(bH[nt], sb + AOFF_KH + off);
                ldsm2(bL[nt], sb + AOFF_KL + off);
            }
#pragma unroll
            for (int mt = 0; mt < 2; mt++)
#pragma unroll
                for (int nt = 0; nt < 2; nt++) {
                    mma16816(sa[mt][nt], aH[mt], bH[nt]);
                    mma16816(sa[mt][nt], aH[mt], bL[nt]);
                    mma16816(sa[mt][nt], aL[mt], bH[nt]);
                }
        }

        // write S fragments (stride 66 floats)
        float* Sbuf = (float*)(sm + AOFF_S);
#pragma unroll
        for (int mt = 0; mt < 2; mt++)
#pragma unroll
            for (int nt = 0; nt < 2; nt++) {
                int r = wmq + mt * 16 + (lane >> 2);
                int c = wnq + nt * 8 + (lane & 3) * 2;
                *(float2*)(Sbuf + r * 66 + c) = make_float2(sa[mt][nt][0], sa[mt][nt][1]);
                *(float2*)(Sbuf + (r + 8) * 66 + c) = make_float2(sa[mt][nt][2], sa[mt][nt][3]);
            }
        __syncthreads();

        // ---- online softmax: warp wid owns rows wid*8..+7, 4 lanes/row ----
        {
            int row = wid * 8 + (lane >> 2);
            int lq = lane & 3;
            float* Srow = (float*)(sm + AOFF_S) + row * 66;
            float vals[16];
            float mx = -1e30f;
#pragma unroll
            for (int i = 0; i < 16; i++) {
                vals[i] = Srow[lq + i * 4];
                mx = fmaxf(mx, vals[i]);
            }
            mx = fmaxf(mx, __shfl_xor_sync(0xffffffffu, mx, 1));
            mx = fmaxf(mx, __shfl_xor_sync(0xffffffffu, mx, 2));
            float mold = sM[row];
            float mnew = fmaxf(mold, mx);
            float fs = __expf(mold - mnew);
            __nv_bfloat16* Ph = (__nv_bfloat16*)(sm + AOFF_PH) + row * 72;
            __nv_bfloat16* Pl = (__nv_bfloat16*)(sm + AOFF_PL) + row * 72;
            float sum = 0.f;
#pragma unroll
            for (int i = 0; i < 16; i++) {
                float p = __expf(vals[i] - mnew);
                sum += p;
                __nv_bfloat16 ph = __float2bfloat16(p);
                Ph[lq + i * 4] = ph;
                Pl[lq + i * 4] = __float2bfloat16(p - __bfloat162float(ph));
            }
            sum += __shfl_xor_sync(0xffffffffu, sum, 1);
            sum += __shfl_xor_sync(0xffffffffu, sum, 2);
            if (lq == 0) {
                sM[row] = mnew;
                sL[row] = sL[row] * fs + sum;
                sF[row] = fs;
            }
        }
        CP_WAIT0();          // V arrived
        __syncthreads();

        // ---- acc = acc*fs + P V (bf16x3) ----
        {
            float f0 = sF[wmp + (lane >> 2)];
            float f1 = sF[wmp + (lane >> 2) + 8];
#pragma unroll
            for (int nt = 0; nt < 5; nt++) {
                acc[nt][0] *= f0; acc[nt][1] *= f0;
                acc[nt][2] *= f1; acc[nt][3] *= f1;
            }
#pragma unroll
            for (int ks = 0; ks < 4; ks++) {
                uint32_t pH[4], pL[4];
                uint32_t poff = (uint32_t)((wmp + arow) * 144 + ks * 32 + acolh);
                ldsm4(pH, sb + AOFF_PH + poff);
                ldsm4(pL, sb + AOFF_PL + poff);
#pragma unroll
                for (int nt = 0; nt < 5; nt++) {
                    uint32_t vH[2], vL[2];
                    uint32_t voff = (uint32_t)((ks * 16 + (lane & 15)) * 176 +
                                               (wnp + nt * 8) * 2);
                    ldsm2t(vH, sb + AOFF_VH + voff);
                    ldsm2t(vL, sb + AOFF_VL + voff);
                    mma16816(acc[nt], pH, vH);
                    mma16816(acc[nt], pH, vL);
                    mma16816(acc[nt], pL, vH);
                }
            }
        }
        __syncthreads();

        if (cc + 1 < 8) issue_kv(cc + 1);
    }

    // epilogue: divide by l, split to bf16 hi/lo, write ctx
    {
        float linv0 = 1.f / sL[wmp + (lane >> 2)];
        float linv1 = 1.f / sL[wmp + (lane >> 2) + 8];
        int r0 = q0 + wmp + (lane >> 2);
#pragma unroll
        for (int nt = 0; nt < 5; nt++) {
            int col = h * HD + wnp + nt * 8 + (lane & 3) * 2;
            float x0 = acc[nt][0] * linv0, y0 = acc[nt][1] * linv0;
            float x1 = acc[nt][2] * linv1, y1 = acc[nt][3] * linv1;
            size_t a0 = (size_t)r0 * DIM + col;
            size_t a1 = a0 + (size_t)8 * DIM;
            __nv_bfloat16 hx0 = __float2bfloat16(x0), hy0 = __float2bfloat16(y0);
            __nv_bfloat16 hx1 = __float2bfloat16(x1), hy1 = __float2bfloat16(y1);
            __nv_bfloat162 t;
            t.x = hx0; t.y = hy0; *(__nv_bfloat162*)(ch + a0) = t;
            t.x = __float2bfloat16(x0 - __bfloat162float(hx0));
            t.y = __float2bfloat16(y0 - __bfloat162float(hy0));
            *(__nv_bfloat162*)(cl + a0) = t;
            t.x = hx1; t.y = hy1; *(__nv_bfloat162*)(ch + a1) = t;
            t.x = __float2bfloat16(x1 - __bfloat162float(hx1));
            t.y = __float2bfloat16(y1 - __bfloat162float(hy1));
            *(__nv_bfloat162*)(cl + a1) = t;
        }
    }
}

// ---------------------------------------------------------------------------
extern "C" void kernel_launch(void* const* d_in, const int* in_sizes, int n_in,
                              void* d_out, int out_size)
{
    const float* hs   = (const float*)d_in[0];
    const float* cosb = (const float*)d_in[1];
    const float* sinb = (const float*)d_in[2];
    const float* wq   = (const float*)d_in[3];
    const float* bq   = (const float*)d_in[4];
    const float* wk   = (const float*)d_in[5];
    const float* bk   = (const float*)d_in[6];
    const float* wv   = (const float*)d_in[7];
    const float* bv   = (const float*)d_in[8];
    const float* wo   = (const float*)d_in[9];
    const float* bo   = (const float*)d_in[10];
    float* out = (float*)d_out;

    float *qp, *kp, *vp;
    cudaGetSymbolAddress((void**)&qp, g_q);
    cudaGetSymbolAddress((void**)&kp, g_k);
    cudaGetSymbolAddress((void**)&vp, g_v);
    __nv_bfloat16 *ah, *al, *wh, *wl, *ch, *cl;
    cudaGetSymbolAddress((void**)&ah, g_ah);
    cudaGetSymbolAddress((void**)&al, g_al);
    cudaGetSymbolAddress((void**)&wh, g_wh);
    cudaGetSymbolAddress((void**)&wl, g_wl);
    cudaGetSymbolAddress((void**)&ch, g_ch);
    cudaGetSymbolAddress((void**)&cl, g_cl);

    cudaFuncSetAttribute(gemm_hmma,
                         cudaFuncAttributeMaxDynamicSharedMemorySize, GEMM_SMEM);
    cudaFuncSetAttribute(attn_mma,
                         cudaFuncAttributeMaxDynamicSharedMemorySize, ATTN_SMEM);

    // 1) split inputs to bf16 hi/lo
    split_hs<<<(S * DIM) / 256, 256>>>(hs, ah, al, S * DIM);
    split_w4<<<dim3((DIM * DIM) / 256, 4), 256>>>(wq, wk, wv, wo, wh, wl);

    // 2) QKV projections
    gemm_hmma<<<dim3(DIM / GBN, S / GBM, 3), 256, GEMM_SMEM>>>(
        ah, al, wh, wl, 0, bq, bk, bv, qp, kp, vp);

    // 3) rope + scale + split + per-head pack
    pack_qkv<<<S, 256>>>(cosb, sinb);

    // 4) attention (writes ctx hi/lo bf16 directly)
    attn_mma<<<dim3(8, NH, NSEG), 256, ATTN_SMEM>>>(ch, cl);

    // 5) O projection
    gemm_hmma<<<dim3(DIM / GBN, S / GBM, 1), 256, GEMM_SMEM>>>(
        ch, cl, wh, wl, 3, bo, bo, bo, out, out, out);
}

// round 7
// speedup vs baseline: 4.5213x; 1.0844x over previous
#include <cuda_runtime.h>
#include <cuda_bf16.h>
#include <cstdint>
#include <math.h>

#define S    3072
#define DIM  1280
#define NH   16
#define HD   80
#define SEG  512
#define NSEG 6

// ---------------- scratch (__device__ globals; no allocs allowed) ----------
__device__ float g_q[S * DIM];
__device__ float g_k[S * DIM];
__device__ float g_v[S * DIM];

__device__ __nv_bfloat16 g_ah[S * DIM];
__device__ __nv_bfloat16 g_al[S * DIM];
__device__ __nv_bfloat16 g_wh[4 * DIM * DIM];
__device__ __nv_bfloat16 g_wl[4 * DIM * DIM];
__device__ __nv_bfloat16 g_ch[S * DIM];
__device__ __nv_bfloat16 g_cl[S * DIM];

__device__ __nv_bfloat16 g_qh[NH * S * HD];
__device__ __nv_bfloat16 g_ql[NH * S * HD];
__device__ __nv_bfloat16 g_kh[NH * S * HD];
__device__ __nv_bfloat16 g_kl[NH * S * HD];
__device__ __nv_bfloat16 g_vh[NH * S * HD];
__device__ __nv_bfloat16 g_vl[NH * S * HD];

// ---------------- PTX helpers (sm_80-era, arch-neutral) --------------------
__device__ __forceinline__ uint32_t smem_u32(const void* p) {
    uint32_t a;
    asm("{ .reg .u64 t; cvta.to.shared.u64 t, %1; cvt.u32.u64 %0, t; }"
        : "=r"(a) : "l"(p));
    return a;
}
__device__ __forceinline__ void ldsm4(uint32_t* r, uint32_t addr) {
    asm volatile("ldmatrix.sync.aligned.m8n8.x4.shared.b16 {%0,%1,%2,%3}, [%4];"
                 : "=r"(r[0]), "=r"(r[1]), "=r"(r[2]), "=r"(r[3]) : "r"(addr));
}
__device__ __forceinline__ void ldsm2(uint32_t* r, uint32_t addr) {
    asm volatile("ldmatrix.sync.aligned.m8n8.x2.shared.b16 {%0,%1}, [%2];"
                 : "=r"(r[0]), "=r"(r[1]) : "r"(addr));
}
__device__ __forceinline__ void ldsm4t(uint32_t* r, uint32_t addr) {
    asm volatile("ldmatrix.sync.aligned.m8n8.x4.trans.shared.b16 {%0,%1,%2,%3}, [%4];"
                 : "=r"(r[0]), "=r"(r[1]), "=r"(r[2]), "=r"(r[3]) : "r"(addr));
}
__device__ __forceinline__ void mma16816(float* d, const uint32_t* a, const uint32_t* b) {
    asm volatile(
        "mma.sync.aligned.m16n8k16.row.col.f32.bf16.bf16.f32 "
        "{%0,%1,%2,%3}, {%4,%5,%6,%7}, {%8,%9}, {%0,%1,%2,%3};"
        : "+f"(d[0]), "+f"(d[1]), "+f"(d[2]), "+f"(d[3])
        : "r"(a[0]), "r"(a[1]), "r"(a[2]), "r"(a[3]), "r"(b[0]), "r"(b[1]));
}

#define CP_ASYNC16(dst, src) \
    asm volatile("cp.async.cg.shared.global [%0], [%1], 16;" :: "r"(dst), "l"(src))
#define CP_COMMIT() asm volatile("cp.async.commit_group;")
#define CP_WAIT3()  asm volatile("cp.async.wait_group 3;")
#define CP_WAIT2()  asm volatile("cp.async.wait_group 2;")
#define CP_WAIT1()  asm volatile("cp.async.wait_group 1;")
#define CP_WAIT0()  asm volatile("cp.async.wait_group 0;")

// pack two fp32 into bf16x2 hi, return hi bits, set lo bits
__device__ __forceinline__ uint32_t pk2(float x, float y, uint32_t& lo) {
    __nv_bfloat162 h, l;
    h.x = __float2bfloat16(x); h.y = __float2bfloat16(y);
    l.x = __float2bfloat16(x - __bfloat162float(h.x));
    l.y = __float2bfloat16(y - __bfloat162float(h.y));
    lo = *(uint32_t*)&l;
    return *(uint32_t*)&h;
}

// ---------------- fp32 -> bf16 hi/lo split (vectorized) ---------------------
__device__ __forceinline__ void split4(float4 v, uint2& ho, uint2& lo) {
    uint32_t l0, l1;
    uint32_t h0 = pk2(v.x, v.y, l0);
    uint32_t h1 = pk2(v.z, v.w, l1);
    ho = make_uint2(h0, h1);
    lo = make_uint2(l0, l1);
}

__global__ void split_hs(const float4* __restrict__ src,
                         uint2* __restrict__ hi, uint2* __restrict__ lo, int n4) {
    int i = blockIdx.x * blockDim.x + threadIdx.x;
    if (i < n4) {
        uint2 h, l;
        split4(src[i], h, l);
        hi[i] = h; lo[i] = l;
    }
}

__global__ void split_w4(const float4* __restrict__ s0, const float4* __restrict__ s1,
                         const float4* __restrict__ s2, const float4* __restrict__ s3,
                         uint2* __restrict__ hi, uint2* __restrict__ lo) {
    int z = blockIdx.y;
    const float4* s = (z == 0) ? s0 : (z == 1) ? s1 : (z == 2) ? s2 : s3;
    size_t base = (size_t)z * (DIM * DIM / 4);
    int i = blockIdx.x * blockDim.x + threadIdx.x;
    uint2 h, l;
    split4(s[i], h, l);
    hi[base + i] = h; lo[base + i] = l;
}

// ---------------- HMMA bf16x3 GEMM (unchanged) ------------------------------
#define GBM 128
#define GBN 128
#define NCHUNK (DIM / 32)
#define TSTRIDE 80
#define TILE_B  (128 * TSTRIDE)
#define STAGE_B (4 * TILE_B)
#define GEMM_SMEM (2 * STAGE_B)

__global__ __launch_bounds__(256) void gemm_hmma(
    const __nv_bfloat16* __restrict__ Ahi, const __nv_bfloat16* __restrict__ Alo,
    const __nv_bfloat16* __restrict__ Whi_base, const __nv_bfloat16* __restrict__ Wlo_base,
    int zoff,
    const float* __restrict__ bias0, const float* __restrict__ bias1, const float* __restrict__ bias2,
    float* __restrict__ C0, float* __restrict__ C1, float* __restrict__ C2)
{
    extern __shared__ char smem[];
    const uint32_t sb = smem_u32(smem);
    const int tid  = threadIdx.x;
    const int wid  = tid >> 5;
    const int lane = tid & 31;

    const int z = blockIdx.z;
    const __nv_bfloat16* Wh = Whi_base + (size_t)(zoff + z) * DIM * DIM;
    const __nv_bfloat16* Wl = Wlo_base + (size_t)(zoff + z) * DIM * DIM;
    const float* bias = (z == 0) ? bias0 : (z == 1) ? bias1 : bias2;
    float* C = (z == 0) ? C0 : (z == 1) ? C1 : C2;

    const int m0 = blockIdx.y * GBM;
    const int n0 = blockIdx.x * GBN;
    const int wm = (wid & 1) * 64;
    const int wn = (wid >> 1) * 32;

    const int tile = tid >> 6;
    const int t64  = tid & 63;
    const char* gsrc;
    if (tile == 0)      gsrc = (const char*)(Ahi + (size_t)m0 * DIM);
    else if (tile == 1) gsrc = (const char*)(Alo + (size_t)m0 * DIM);
    else if (tile == 2) gsrc = (const char*)(Wh  + (size_t)n0 * DIM);
    else                gsrc = (const char*)(Wl  + (size_t)n0 * DIM);
    const uint32_t sdst0 = sb + tile * TILE_B;

    float acc[4][4][4];
#pragma unroll
    for (int mt = 0; mt < 4; mt++)
#pragma unroll
        for (int nt = 0; nt < 4; nt++)
#pragma unroll
            for (int i = 0; i < 4; i++) acc[mt][nt][i] = 0.f;

    {
        const char* s = gsrc;
        uint32_t d = sdst0;
#pragma unroll
        for (int i = 0; i < 8; i++) {
            int idx = i * 64 + t64;
            int row = idx >> 2, c16 = idx & 3;
            CP_ASYNC16(d + row * TSTRIDE + c16 * 16,
                       s + (size_t)row * (DIM * 2) + c16 * 16);
        }
        CP_COMMIT();
    }

    const int arow = lane & 15;
    const int acolh = (lane >> 4) * 16;
    const int brow = lane & 7;
    const int bcolh = ((lane >> 3) & 1) * 16;

    for (int c = 0; c < NCHUNK; c++) {
        if (c + 1 < NCHUNK) {
            const char* s = gsrc + (size_t)(c + 1) * 64;
            uint32_t d = sdst0 + ((c + 1) & 1) * STAGE_B;
#pragma unroll
            for (int i = 0; i < 8; i++) {
                int idx = i * 64 + t64;
                int row = idx >> 2, c16 = idx & 3;
                CP_ASYNC16(d + row * TSTRIDE + c16 * 16,
                           s + (size_t)row * (DIM * 2) + c16 * 16);
            }
            CP_COMMIT();
            CP_WAIT1();
        } else {
            CP_WAIT0();
        }
        __syncthreads();

        const uint32_t stage = sb + (c & 1) * STAGE_B;
        const uint32_t sAh = stage;
        const uint32_t sAl = stage + TILE_B;
        const uint32_t sWh = stage + 2 * TILE_B;
        const uint32_t sWl = stage + 3 * TILE_B;

#pragma unroll
        for (int ks = 0; ks < 2; ks++) {
            uint32_t ah[4][4], al[4][4], bh[4][2], bl[4][2];
            const int acol = ks * 32 + acolh;
            const int bcol = ks * 32 + bcolh;
#pragma unroll
            for (int mt = 0; mt < 4; mt++) {
                uint32_t off = (uint32_t)((wm + mt * 16 + arow) * TSTRIDE + acol);
                ldsm4(ah[mt], sAh + off);
                ldsm4(al[mt], sAl + off);
            }
#pragma unroll
            for (int nt = 0; nt < 4; nt++) {
                uint32_t off = (uint32_t)((wn + nt * 8 + brow) * TSTRIDE + bcol);
                ldsm2(bh[nt], sWh + off);
                ldsm2(bl[nt], sWl + off);
            }
#pragma unroll
            for (int mt = 0; mt < 4; mt++)
#pragma unroll
                for (int nt = 0; nt < 4; nt++) {
                    mma16816(acc[mt][nt], ah[mt], bh[nt]);
                    mma16816(acc[mt][nt], ah[mt], bl[nt]);
                    mma16816(acc[mt][nt], al[mt], bh[nt]);
                }
        }
        __syncthreads();
    }

    const int r0 = lane >> 2;
    const int c0 = (lane & 3) * 2;
#pragma unroll
    for (int mt = 0; mt < 4; mt++) {
#pragma unroll
        for (int nt = 0; nt < 4; nt++) {
            int gm = m0 + wm + mt * 16 + r0;
            int gn = n0 + wn + nt * 8 + c0;
            float2 bv = *(const float2*)(bias + gn);
            float2 o0, o1;
            o0.x = acc[mt][nt][0] + bv.x;
            o0.y = acc[mt][nt][1] + bv.y;
            o1.x = acc[mt][nt][2] + bv.x;
            o1.y = acc[mt][nt][3] + bv.y;
            *(float2*)(C + (size_t)gm * DIM + gn) = o0;
            *(float2*)(C + (size_t)(gm + 8) * DIM + gn) = o1;
        }
    }
}

// ---------------- pack: rope + scale + split + per-head relayout ------------
__global__ void pack_qkv(const float* __restrict__ cosb,
                         const float* __restrict__ sinb)
{
    const int s = blockIdx.x;
    const int tid = threadIdx.x;
    const float scale = 0.11180339887498949f;

    for (int p = tid; p < NH * 40; p += 256) {
        int h = p / 40, d = p % 40;
        float c  = cosb[s * HD + d];
        float sn = sinb[s * HD + d];
        size_t ib = (size_t)s * DIM + h * HD + d;
        size_t ob = ((size_t)h * S + s) * HD + d;

        float q1 = g_q[ib], q2 = g_q[ib + 40];
        float qo1 = (q1 * c - q2 * sn) * scale;
        float qo2 = (q2 * c + q1 * sn) * scale;
        __nv_bfloat16 h1 = __float2bfloat16(qo1);
        __nv_bfloat16 h2 = __float2bfloat16(qo2);
        g_qh[ob]      = h1;
        g_qh[ob + 40] = h2;
        g_ql[ob]      = __float2bfloat16(qo1 - __bfloat162float(h1));
        g_ql[ob + 40] = __float2bfloat16(qo2 - __bfloat162float(h2));

        float k1 = g_k[ib], k2 = g_k[ib + 40];
        float ko1 = k1 * c - k2 * sn;
        float ko2 = k2 * c + k1 * sn;
        __nv_bfloat16 kh1 = __float2bfloat16(ko1);
        __nv_bfloat16 kh2 = __float2bfloat16(ko2);
        g_kh[ob]      = kh1;
        g_kh[ob + 40] = kh2;
        g_kl[ob]      = __float2bfloat16(ko1 - __bfloat162float(kh1));
        g_kl[ob + 40] = __float2bfloat16(ko2 - __bfloat162float(kh2));
    }

    for (int e = tid; e < DIM; e += 256) {
        int h = e / HD, d = e % HD;
        float v = g_v[(size_t)s * DIM + e];
        __nv_bfloat16 vh = __float2bfloat16(v);
        size_t ob = ((size_t)h * S + s) * HD + d;
        g_vh[ob] = vh;
        g_vl[ob] = __float2bfloat16(v - __bfloat162float(vh));
    }
}

// ---------------- flash attention: register S/P, double-buffered KV ---------
// CTA: 64 q rows x one head x one segment; 8 chunks of 64 keys.
// QK warps: 4m x 2n (warp tile 16x32). PV: each warp accumulates its k-half
// over all 80 cols; halves combined in epilogue via smem.
// ATS MUST be a multiple of 16 (cp.async/ldmatrix alignment).
#define ATS 176                       // smem row stride (bytes)
#define ATB (64 * ATS)                // 11264 per tile
#define AQH 0
#define AQL ATB
#define AKV0 (2 * ATB)                // buf0: KH,KL,VH,VL
#define AKV1 (6 * ATB)                // buf1
#define APMAX (10 * ATB)              // float[2][64]
#define APLS  (APMAX + 512)           // float[64] upper-half l
#define ATTN_SMEM (APLS + 256)        // 113408 B

__global__ __launch_bounds__(256, 2) void attn_mma(__nv_bfloat16* __restrict__ ch,
                                                   __nv_bfloat16* __restrict__ cl)
{
    extern __shared__ char sm[];
    const uint32_t sb = smem_u32(sm);
    const int tid = threadIdx.x;
    const int wid = tid >> 5;
    const int lane = tid & 31;

    const int qt = blockIdx.x;
    const int h  = blockIdx.y;
    const int sg = blockIdx.z;
    const int s0 = sg * SEG;
    const int q0 = s0 + qt * 64;
    const size_t hb = (size_t)h * S * HD;

    const int wm = (wid & 3) * 16;      // row group
    const int wh = wid >> 2;            // column half (0: cols 0-31, 1: 32-63)
    const int wn = wh * 32;

    float* pmax = (float*)(sm + APMAX);
    float* plsum = (float*)(sm + APLS);

    const char* qhp = (const char*)(g_qh + hb + (size_t)q0 * HD);
    const char* qlp = (const char*)(g_ql + hb + (size_t)q0 * HD);
    const char* khp = (const char*)(g_kh + hb + (size_t)s0 * HD);
    const char* klp = (const char*)(g_kl + hb + (size_t)s0 * HD);
    const char* vhp = (const char*)(g_vh + hb + (size_t)s0 * HD);
    const char* vlp = (const char*)(g_vl + hb + (size_t)s0 * HD);

    // cp.async one hi/lo tile pair (64 rows x 160B each)
    auto cp_pair = [&](uint32_t dH, uint32_t dL, const char* srcH, const char* srcL, int rb) {
#pragma unroll
        for (int i = 0; i < 5; i++) {
            int f = i * 256 + tid;
            int sel = f >= 640;
            int g = f - (sel ? 640 : 0);
            int r = g / 10, c = g - r * 10;
            CP_ASYNC16(sb + (sel ? dL : dH) + r * ATS + c * 16,
                       (sel ? srcL : srcH) + (size_t)(rb + r) * 160 + c * 16);
        }
    };

    // prologue: group1 = Q + K0; group2 = V0; group3 = K1; group4 = V1
    cp_pair(AQH, AQL, qhp, qlp, 0);
    cp_pair(AKV0, AKV0 + ATB, khp, klp, 0);
    CP_COMMIT();
    cp_pair(AKV0 + 2 * ATB, AKV0 + 3 * ATB, vhp, vlp, 0);
    CP_COMMIT();
    cp_pair(AKV1, AKV1 + ATB, khp, klp, 64);
    CP_COMMIT();
    cp_pair(AKV1 + 2 * ATB, AKV1 + 3 * ATB, vhp, vlp, 64);
    CP_COMMIT();

    float acc[10][4];
#pragma unroll
    for (int nt = 0; nt < 10; nt++)
#pragma unroll
        for (int i = 0; i < 4; i++) acc[nt][i] = 0.f;

    float mold0 = -1e30f, mold1 = -1e30f;   // rows r, r+8
    float lsum0 = 0.f, lsum1 = 0.f;

    const int qrow = wm + (lane & 15);
    const uint32_t qcoloff = (uint32_t)((lane >> 4) * 16);
    const int krowa = wn + ((lane >> 4) << 3) + (lane & 7);
    const uint32_t kcoloff = (uint32_t)(((lane >> 3) & 1) * 16);
    const int r4 = lane >> 2;
    const int q2 = (lane & 3) * 2;

    for (int c = 0; c < 8; c++) {
        const uint32_t kv = sb + ((c & 1) ? AKV1 : AKV0);
        const uint32_t sKH = kv, sKL = kv + ATB, sVH = kv + 2 * ATB, sVL = kv + 3 * ATB;

        if (c == 7) { CP_WAIT1(); } else { CP_WAIT3(); }
        __syncthreads();

        // ---- S = Q K^T (bf16x3), warp tile 16x32 in registers ----
        float sa[4][4];
#pragma unroll
        for (int nt = 0; nt < 4; nt++)
#pragma unroll
            for (int i = 0; i < 4; i++) sa[nt][i] = 0.f;

#pragma unroll
        for (int ks = 0; ks < 5; ks++) {
            uint32_t qh4[4], ql4[4], kh[8], kl[8];
            uint32_t qoff = (uint32_t)(qrow * ATS + ks * 32) + qcoloff;
            ldsm4(qh4, sb + AQH + qoff);
            ldsm4(ql4, sb + AQL + qoff);
            uint32_t koff0 = (uint32_t)(krowa * ATS + ks * 32) + kcoloff;
            ldsm4(kh,     sKH + koff0);
            ldsm4(kh + 4, sKH + koff0 + 16 * ATS);
            ldsm4(kl,     sKL + koff0);
            ldsm4(kl + 4, sKL + koff0 + 16 * ATS);
#pragma unroll
            for (int nt = 0; nt < 4; nt++) {
                mma16816(sa[nt], qh4, kh + nt * 2);
                mma16816(sa[nt], qh4, kl + nt * 2);
                mma16816(sa[nt], ql4, kh + nt * 2);
            }
        }

        // ---- partial row max (quad reduce), publish to smem ----
        float mx0 = fmaxf(fmaxf(sa[0][0], sa[0][1]), fmaxf(sa[1][0], sa[1][1]));
        mx0 = fmaxf(mx0, fmaxf(fmaxf(sa[2][0], sa[2][1]), fmaxf(sa[3][0], sa[3][1])));
        float mx1 = fmaxf(fmaxf(sa[0][2], sa[0][3]), fmaxf(sa[1][2], sa[1][3]));
        mx1 = fmaxf(mx1, fmaxf(fmaxf(sa[2][2], sa[2][3]), fmaxf(sa[3][2], sa[3][3])));
        mx0 = fmaxf(mx0, __shfl_xor_sync(0xffffffffu, mx0, 1));
        mx0 = fmaxf(mx0, __shfl_xor_sync(0xffffffffu, mx0, 2));
        mx1 = fmaxf(mx1, __shfl_xor_sync(0xffffffffu, mx1, 1));
        mx1 = fmaxf(mx1, __shfl_xor_sync(0xffffffffu, mx1, 2));
        if ((lane & 3) == 0) {
            pmax[wh * 64 + wm + r4] = mx0;
            pmax[wh * 64 + wm + 8 + r4] = mx1;
        }

        if (c == 7) { CP_WAIT0(); } else { CP_WAIT2(); }
        __syncthreads();   // pmax + V visible

        // ---- softmax on register fragments ----
        float ma0 = fmaxf(pmax[wm + r4], pmax[64 + wm + r4]);
        float ma1 = fmaxf(pmax[wm + 8 + r4], pmax[64 + wm + 8 + r4]);
        float mn0 = fmaxf(mold0, ma0);
        float mn1 = fmaxf(mold1, ma1);
        float fs0 = __expf(mold0 - mn0);
        float fs1 = __expf(mold1 - mn1);
        mold0 = mn0; mold1 = mn1;

        float s0r = 0.f, s1r = 0.f;
#pragma unroll
        for (int nt = 0; nt < 4; nt++) {
            sa[nt][0] = __expf(sa[nt][0] - mn0);
            sa[nt][1] = __expf(sa[nt][1] - mn0);
            sa[nt][2] = __expf(sa[nt][2] - mn1);
            sa[nt][3] = __expf(sa[nt][3] - mn1);
            s0r += sa[nt][0] + sa[nt][1];
            s1r += sa[nt][2] + sa[nt][3];
        }
        s0r += __shfl_xor_sync(0xffffffffu, s0r, 1);
        s0r += __shfl_xor_sync(0xffffffffu, s0r, 2);
        s1r += __shfl_xor_sync(0xffffffffu, s1r, 1);
        s1r += __shfl_xor_sync(0xffffffffu, s1r, 2);
        lsum0 = lsum0 * fs0 + s0r;
        lsum1 = lsum1 * fs1 + s1r;

#pragma unroll
        for (int nt = 0; nt < 10; nt++) {
            acc[nt][0] *= fs0; acc[nt][1] *= fs0;
            acc[nt][2] *= fs1; acc[nt][3] *= fs1;
        }

        // ---- PV over this warp's k-half (bf16x3) ----
#pragma unroll
        for (int kb = 0; kb < 2; kb++) {
            uint32_t aH[4], aL[4];
            aH[0] = pk2(sa[2 * kb][0], sa[2 * kb][1], aL[0]);
            aH[1] = pk2(sa[2 * kb][2], sa[2 * kb][3], aL[1]);
            aH[2] = pk2(sa[2 * kb + 1][0], sa[2 * kb + 1][1], aL[2]);
            aH[3] = pk2(sa[2 * kb + 1][2], sa[2 * kb + 1][3], aL[3]);
            const int vrow = wn + kb * 16 + (lane & 15);
#pragma unroll
            for (int np = 0; np < 5; np++) {
                uint32_t vh4[4], vl4[4];
                uint32_t voff = (uint32_t)(vrow * ATS + (np * 16 + ((lane >> 4) << 3)) * 2);
                ldsm4t(vh4, sVH + voff);
                ldsm4t(vl4, sVL + voff);
                mma16816(acc[np * 2], aH, vh4);
                mma16816(acc[np * 2], aH, vl4);
                mma16816(acc[np * 2], aL, vh4);
                mma16816(acc[np * 2 + 1], aH, vh4 + 2);
                mma16816(acc[np * 2 + 1], aH, vl4 + 2);
                mma16816(acc[np * 2 + 1], aL, vh4 + 2);
            }
        }
        __syncthreads();   // all warps done with buf c

        if (c + 2 < 8) {
            const uint32_t nb = sb + ((c & 1) ? AKV1 : AKV0);
            cp_pair(nb - sb, nb - sb + ATB, khp, klp, (c + 2) * 64);
            CP_COMMIT();
            cp_pair(nb - sb + 2 * ATB, nb - sb + 3 * ATB, vhp, vlp, (c + 2) * 64);
            CP_COMMIT();
        }
    }

    // ---- epilogue: combine column halves, normalize, write ctx hi/lo ----
    float* cb = (float*)(sm + AKV0);   // 4 groups x 16 rows x 80 cols fp32
    if (wh == 1) {
#pragma unroll
        for (int nt = 0; nt < 10; nt++) {
            int cc = nt * 8 + q2;
            cb[(wm + r4) * 80 + cc]     = acc[nt][0];
            cb[(wm + r4) * 80 + cc + 1] = acc[nt][1];
            cb[(wm + r4 + 8) * 80 + cc]     = acc[nt][2];
            cb[(wm + r4 + 8) * 80 + cc + 1] = acc[nt][3];
        }
        if ((lane & 3) == 0) {
            plsum[wm + r4] = lsum0;
            plsum[wm + r4 + 8] = lsum1;
        }
    }
    __syncthreads();
    if (wh == 0) {
        float li0 = 1.f / (lsum0 + plsum[wm + r4]);
        float li1 = 1.f / (lsum1 + plsum[wm + r4 + 8]);
        int gr0 = q0 + wm + r4;
#pragma unroll
        for (int nt = 0; nt < 10; nt++) {
            int col = h * HD + nt * 8 + q2;
            float x0 = (acc[nt][0] + cb[(wm + r4) * 80 + nt * 8 + q2]) * li0;
            float y0 = (acc[nt][1] + cb[(wm + r4) * 80 + nt * 8 + q2 + 1]) * li0;
            float x1 = (acc[nt][2] + cb[(wm + r4 + 8) * 80 + nt * 8 + q2]) * li1;
            float y1 = (acc[nt][3] + cb[(wm + r4 + 8) * 80 + nt * 8 + q2 + 1]) * li1;
            size_t a0 = (size_t)gr0 * DIM + col;
            size_t a1 = a0 + (size_t)8 * DIM;
            uint32_t lo;
            uint32_t hi = pk2(x0, y0, lo);
            *(uint32_t*)(ch + a0) = hi;
            *(uint32_t*)(cl + a0) = lo;
            hi = pk2(x1, y1, lo);
            *(uint32_t*)(ch + a1) = hi;
            *(uint32_t*)(cl + a1) = lo;
        }
    }
}

// ---------------------------------------------------------------------------
extern "C" void kernel_launch(void* const* d_in, const int* in_sizes, int n_in,
                              void* d_out, int out_size)
{
    const float* hs   = (const float*)d_in[0];
    const float* cosb = (const float*)d_in[1];
    const float* sinb = (const float*)d_in[2];
    const float* wq   = (const float*)d_in[3];
    const float* bq   = (const float*)d_in[4];
    const float* wk   = (const float*)d_in[5];
    const float* bk   = (const float*)d_in[6];
    const float* wv   = (const float*)d_in[7];
    const float* bv   = (const float*)d_in[8];
    const float* wo   = (const float*)d_in[9];
    const float* bo   = (const float*)d_in[10];
    float* out = (float*)d_out;

    float *qp, *kp, *vp;
    cudaGetSymbolAddress((void**)&qp, g_q);
    cudaGetSymbolAddress((void**)&kp, g_k);
    cudaGetSymbolAddress((void**)&vp, g_v);
    __nv_bfloat16 *ah, *al, *wh, *wl, *ch, *cl;
    cudaGetSymbolAddress((void**)&ah, g_ah);
    cudaGetSymbolAddress((void**)&al, g_al);
    cudaGetSymbolAddress((void**)&wh, g_wh);
    cudaGetSymbolAddress((void**)&wl, g_wl);
    cudaGetSymbolAddress((void**)&ch, g_ch);
    cudaGetSymbolAddress((void**)&cl, g_cl);

    cudaFuncSetAttribute(gemm_hmma,
                         cudaFuncAttributeMaxDynamicSharedMemorySize, GEMM_SMEM);
    cudaFuncSetAttribute(attn_mma,
                         cudaFuncAttributeMaxDynamicSharedMemorySize, ATTN_SMEM);

    split_hs<<<(S * DIM / 4) / 256, 256>>>((const float4*)hs, (uint2*)ah, (uint2*)al,
                                           S * DIM / 4);
    split_w4<<<dim3((DIM * DIM / 4) / 256, 4), 256>>>(
        (const float4*)wq, (const float4*)wk, (const float4*)wv, (const float4*)wo,
        (uint2*)wh, (uint2*)wl);

    gemm_hmma<<<dim3(DIM / GBN, S / GBM, 3), 256, GEMM_SMEM>>>(
        ah, al, wh, wl, 0, bq, bk, bv, qp, kp, vp);

    pack_qkv<<<S, 256>>>(cosb, sinb);

    attn_mma<<<dim3(8, NH, NSEG), 256, ATTN_SMEM>>>(ch, cl);

    gemm_hmma<<<dim3(DIM / GBN, S / GBM, 1), 256, GEMM_SMEM>>>(
        ch, cl, wh, wl, 3, bo, bo, bo, out, out, out);
}